// round 3
// baseline (speedup 1.0000x reference)
#include <cuda_runtime.h>

#define BB 256
#define TT 256
#define DD 80
#define HH 512
#define GG 2048   // 4*HH
#define NBLK 128
#define NTH 512
#define WSP_E 596     // enc W smem k-stride (floats)
#define WSP_D 516     // dec W smem k-stride
#define HS_STRIDE 68  // h chunk smem stride (floats, 64 + pad)
#define HS_BUF (64*HS_STRIDE)
#define NCH_E 10      // enc chunks: x64, x16, 8x h64
#define NCH_D 8       // dec chunks: 8x h64

// ---------------- device scratch ----------------
__device__ float g_hA[BB*HH];
__device__ float g_hB[BB*HH];
__device__ float g_Wcomb[(size_t)GG*HH];   // dec: W_hh + W_ih * fc_W   [n][k]
__device__ float g_bias_enc[GG];
__device__ float g_bcomb[GG];
__device__ float g_quant[BB*HH];
__device__ float g_tmpT[DD*BB];
__device__ float g_corr[(size_t)BB*GG];
__device__ float g_lossp[BB];
__device__ int   g_idx[BB];
__device__ float g_Hbuf[(size_t)TT*BB*HH];
__device__ unsigned g_bar;

// ---------------- helpers ----------------
__device__ __forceinline__ unsigned long long dupf(float v){
    unsigned long long r; asm("mov.b64 %0, {%1,%1};" : "=l"(r) : "f"(v)); return r;
}
__device__ __forceinline__ float2 ull2f(unsigned long long v){
    float2 r; asm("mov.b64 {%0,%1}, %2;" : "=f"(r.x), "=f"(r.y) : "l"(v)); return r;
}
__device__ __forceinline__ void ffma2(unsigned long long& d, unsigned long long a, unsigned long long b){
    asm("fma.rn.f32x2 %0, %1, %2, %0;" : "+l"(d) : "l"(a), "l"(b));
}
__device__ __forceinline__ float sigf(float x){ return 1.f/(1.f + __expf(-x)); }
__device__ __forceinline__ float tanh_f(float x){ return 2.f/(1.f + __expf(-2.f*x)) - 1.f; }

__device__ __forceinline__ void cpa16(float* dst, const float* src){
    unsigned d = (unsigned)__cvta_generic_to_shared(dst);
    asm volatile("cp.async.cg.shared.global [%0], [%1], 16;" :: "r"(d), "l"(src));
}
__device__ __forceinline__ void cpa_commit(){ asm volatile("cp.async.commit_group;" ::: "memory"); }
__device__ __forceinline__ void cpa_wait0(){ asm volatile("cp.async.wait_group 0;" ::: "memory"); }

__device__ __forceinline__ void grid_sync(unsigned epoch){
    __syncthreads();
    if (threadIdx.x == 0){
        __threadfence();
        atomicAdd(&g_bar, 1u);
        unsigned target = (epoch + 1u) * NBLK;
        unsigned v;
        do {
            asm volatile("ld.acquire.gpu.u32 %0, [%1];" : "=r"(v) : "l"(&g_bar) : "memory");
        } while (v < target);
    }
    __syncthreads();
}

// K-paired MMA: each thread computes 2 rows x 4 gate-outputs.
// hb: h base for this thread's rows; wb: ws + tx*WSP + koff.
template<int N4, int WSP>
__device__ __forceinline__ void mma_k(unsigned long long acc[4][2],
                                      const float* hb, const float* wb){
    #pragma unroll
    for (int k4 = 0; k4 < N4; k4++){
        ulonglong2 h0 = *reinterpret_cast<const ulonglong2*>(hb + k4*4);
        ulonglong2 h1 = *reinterpret_cast<const ulonglong2*>(hb + HS_STRIDE + k4*4);
        #pragma unroll
        for (int q = 0; q < 4; q++){
            ulonglong2 w = *reinterpret_cast<const ulonglong2*>(wb + q*16*WSP + k4*4);
            ffma2(acc[q][0], h0.x, w.x);
            ffma2(acc[q][0], h0.y, w.y);
            ffma2(acc[q][1], h1.x, w.x);
            ffma2(acc[q][1], h1.y, w.y);
        }
    }
}

// ---------------- prep kernels ----------------
__global__ void k_bias(const float* __restrict__ ebi, const float* __restrict__ ebh,
                       const float* __restrict__ dbi, const float* __restrict__ dbh,
                       const float* __restrict__ dWih, const float* __restrict__ fcb){
    int n = blockIdx.x*blockDim.x + threadIdx.x;
    if (n < GG){
        g_bias_enc[n] = ebi[n] + ebh[n];
        float b = dbi[n] + dbh[n];
        const float* w = dWih + (size_t)n*DD;
        #pragma unroll 4
        for (int d = 0; d < DD; d++) b += fcb[d]*w[d];
        g_bcomb[n] = b;
    }
}

__global__ void k_wcomb(const float* __restrict__ dWih, const float* __restrict__ dWhh,
                        const float* __restrict__ fcW){
    __shared__ float sf[DD][64];
    __shared__ float sw[32][DD];
    int nt = blockIdx.x >> 3, kt = blockIdx.x & 7;
    int n0 = nt*32, k0 = kt*64;
    int tid = threadIdx.x;
    for (int idx = tid; idx < DD*64; idx += 256){
        int d = idx >> 6, kk = idx & 63;
        sf[d][kk] = fcW[(size_t)d*HH + k0 + kk];
    }
    for (int idx = tid; idx < 32*DD; idx += 256){
        int nn = idx / DD, d = idx % DD;
        sw[nn][d] = dWih[(size_t)(n0+nn)*DD + d];
    }
    __syncthreads();
    int nn = tid >> 3, kb = (tid & 7)*8;
    float a[8];
    #pragma unroll
    for (int i = 0; i < 8; i++) a[i] = dWhh[(size_t)(n0+nn)*HH + k0 + kb + i];
    for (int d = 0; d < DD; d++){
        float w = sw[nn][d];
        #pragma unroll
        for (int i = 0; i < 8; i++) a[i] += w * sf[d][kb+i];
    }
    #pragma unroll
    for (int i = 0; i < 8; i++) g_Wcomb[(size_t)(n0+nn)*HH + k0 + kb + i] = a[i];
}

__global__ void k_x1(const float* __restrict__ fcW, const float* __restrict__ fcb){
    int b = blockIdx.x, tid = threadIdx.x;
    __shared__ float qs[HH];
    qs[tid]       = g_quant[(size_t)b*HH + tid];
    qs[tid + 256] = g_quant[(size_t)b*HH + tid + 256];
    __syncthreads();
    if (tid < DD){
        const float* w = fcW + (size_t)tid*HH;
        float s = fcb[tid];
        for (int k = 0; k < HH; k++) s += w[k]*qs[k];
        g_tmpT[tid*BB + b] = s;
    }
}

__global__ void k_corr(const float* __restrict__ dWih){
    int n = blockIdx.x, b = threadIdx.x;
    __shared__ float wd[DD];
    if (b < DD) wd[b] = dWih[(size_t)n*DD + b];
    __syncthreads();
    float s = 0.f;
    #pragma unroll 4
    for (int d = 0; d < DD; d++) s += wd[d] * g_tmpT[d*BB + b];
    g_corr[(size_t)b*GG + n] = s;
}

__global__ void k_init(){
    int i = blockIdx.x*blockDim.x + threadIdx.x;
    if (i < BB*HH) g_hA[i] = 0.f;
    if (i == 0) g_bar = 0u;
}
__global__ void k_decinit(){
    int i = blockIdx.x*blockDim.x + threadIdx.x;
    if (i < BB*HH) g_hA[i] = g_quant[i];
    if (i == 0) g_bar = 0u;
}

// ---------------- persistent encoder ----------------
__global__ void __launch_bounds__(NTH, 1) k_encoder(const float* __restrict__ traj,
                                                    const float* __restrict__ eWih,
                                                    const float* __restrict__ eWhh){
    extern __shared__ float sm[];
    float* ws = sm;
    float* hs = sm + 64*WSP_E;
    const int tid = threadIdx.x;
    const int rg = blockIdx.x >> 5, cg = blockIdx.x & 31;
    const int row0 = rg*64, j0 = cg*16;
    const int tx = tid & 15, ty = tid >> 4;   // ty 0..31, rows ty*2..ty*2+1
    const int j = j0 + tx;
    const int lr = tid >> 3, t8 = tid & 7;    // staging: row lr, k-octet t8

    // resident W load (one-time): col c = q*16 + jj
    {
        int c = tid >> 3, l8 = tid & 7;
        int n = (c >> 4)*HH + j0 + (c & 15);
        for (int k0 = l8*4; k0 < DD; k0 += 32)
            *(float4*)&ws[c*WSP_E + k0] = *(const float4*)&eWih[(size_t)n*DD + k0];
        for (int k0 = l8*4; k0 < HH; k0 += 32)
            *(float4*)&ws[c*WSP_E + DD + k0] = *(const float4*)&eWhh[(size_t)n*HH + k0];
    }
    float bias[4];
    #pragma unroll
    for (int q = 0; q < 4; q++) bias[q] = g_bias_enc[q*HH + j];
    float cst[2] = {0.f, 0.f};

    int pb = 0;
    // stage chunk 0 of t=0 (x k0..63)
    {
        const float* src = traj + ((size_t)(row0+lr)*TT + 0)*DD + t8*8;
        float* dst = hs + 0*HS_BUF + lr*HS_STRIDE + t8*8;
        cpa16(dst, src); cpa16(dst+4, src+4);
        cpa_commit(); cpa_wait0();
    }
    __syncthreads();

    for (int t = 0; t < TT; t++){
        const float* hr = (t & 1) ? g_hB : g_hA;
        float*       hw = (t & 1) ? g_hA : g_hB;

        unsigned long long acc[4][2];
        #pragma unroll
        for (int q = 0; q < 4; q++){ acc[q][0] = 0ull; acc[q][1] = 0ull; }

        for (int cn = 0; cn < NCH_E; cn++){
            // prefetch next chunk into buf pb^1
            {
                int nc = cn + 1, nt = t;
                if (nc == NCH_E){ nc = 0; nt = t + 1; }
                if (nt < TT){
                    float* dst = hs + (pb^1)*HS_BUF + lr*HS_STRIDE;
                    if (nc == 0){
                        const float* src = traj + ((size_t)(row0+lr)*TT + nt)*DD + t8*8;
                        cpa16(dst + t8*8, src); cpa16(dst + t8*8 + 4, src + 4);
                    } else if (nc == 1){
                        if (t8 < 4){
                            const float* src = traj + ((size_t)(row0+lr)*TT + nt)*DD + 64 + t8*4;
                            cpa16(dst + t8*4, src);
                        }
                    } else {
                        const float* src = hr + (size_t)(row0+lr)*HH + (nc-2)*64 + t8*8;
                        cpa16(dst + t8*8, src); cpa16(dst + t8*8 + 4, src + 4);
                    }
                }
                cpa_commit();
            }
            // compute chunk cn from buffer pb
            {
                const float* hb = hs + pb*HS_BUF + (ty*2)*HS_STRIDE;
                int koff = (cn == 0) ? 0 : (cn == 1) ? 64 : DD + (cn-2)*64;
                const float* wb = ws + tx*WSP_E + koff;
                if (cn == 1) mma_k<4,  WSP_E>(acc, hb, wb);
                else         mma_k<16, WSP_E>(acc, hb, wb);
            }
            cpa_wait0();
            __syncthreads();
            pb ^= 1;
        }

        // elementwise LSTM (c in registers)
        #pragma unroll
        for (int i = 0; i < 2; i++){
            float2 v0 = ull2f(acc[0][i]);
            float2 v1 = ull2f(acc[1][i]);
            float2 v2 = ull2f(acc[2][i]);
            float2 v3 = ull2f(acc[3][i]);
            float gi = v0.x + v0.y + bias[0];
            float gf = v1.x + v1.y + bias[1];
            float gg = v2.x + v2.y + bias[2];
            float go = v3.x + v3.y + bias[3];
            float cn_ = sigf(gf)*cst[i] + sigf(gi)*tanh_f(gg);
            cst[i] = cn_;
            hw[(size_t)(row0 + ty*2 + i)*HH + j] = sigf(go)*tanh_f(cn_);
        }
        grid_sync((unsigned)t);
    }
}

// ---------------- VQ ----------------
__global__ void k_vq(const float* __restrict__ emb){
    int b = blockIdx.x, tid = threadIdx.x;
    __shared__ float zs[HH];
    __shared__ float rs[256];
    __shared__ int   rk[256];
    zs[tid]       = g_hA[(size_t)b*HH + tid];
    zs[tid + 256] = g_hA[(size_t)b*HH + tid + 256];
    __syncthreads();
    float bestS = 3.4e38f; int bestK = 0;
    #pragma unroll
    for (int kq = 0; kq < 2; kq++){
        int k = tid + kq*256;
        const float* e = emb + (size_t)k*HH;
        float s = 0.f, dt = 0.f;
        for (int jj = 0; jj < HH; jj++){ float ev = e[jj]; s += ev*ev; dt += ev*zs[jj]; }
        float score = s - 2.f*dt;
        if (score < bestS || (score == bestS && k < bestK)){ bestS = score; bestK = k; }
    }
    rs[tid] = bestS; rk[tid] = bestK;
    __syncthreads();
    for (int s = 128; s > 0; s >>= 1){
        if (tid < s){
            if (rs[tid+s] < rs[tid] || (rs[tid+s] == rs[tid] && rk[tid+s] < rk[tid])){
                rs[tid] = rs[tid+s]; rk[tid] = rk[tid+s];
            }
        }
        __syncthreads();
    }
    int idx = rk[0];
    if (tid == 0) g_idx[b] = idx;
    float lp = 0.f;
    #pragma unroll
    for (int kq = 0; kq < 2; kq++){
        int jj = tid + kq*256;
        float q = emb[(size_t)idx*HH + jj];
        g_quant[(size_t)b*HH + jj] = q;
        float dz = q - zs[jj];
        lp += dz*dz;
    }
    __syncthreads();
    rs[tid] = lp;
    __syncthreads();
    for (int s = 128; s > 0; s >>= 1){
        if (tid < s) rs[tid] += rs[tid+s];
        __syncthreads();
    }
    if (tid == 0) g_lossp[b] = rs[0];
}

__global__ void k_vqfinish(float* __restrict__ out){
    const size_t OFF = (size_t)BB*TT*DD;
    int tid = threadIdx.x;
    if (tid == 0){
        float tot = 0.f;
        for (int i = 0; i < BB; i++) tot += g_lossp[i];
        out[OFF] = 1.25f * tot / (float)(BB*HH);
    }
    out[OFF + 1 + tid] = (float)g_idx[tid];
}

// ---------------- persistent decoder ----------------
__global__ void __launch_bounds__(NTH, 1) k_decoder(){
    extern __shared__ float sm[];
    float* ws = sm;
    float* hs = sm + 64*WSP_D;
    const int tid = threadIdx.x;
    const int rg = blockIdx.x >> 5, cg = blockIdx.x & 31;
    const int row0 = rg*64, j0 = cg*16;
    const int tx = tid & 15, ty = tid >> 4;
    const int j = j0 + tx;
    const int lr = tid >> 3, t8 = tid & 7;

    {
        int c = tid >> 3, l8 = tid & 7;
        int n = (c >> 4)*HH + j0 + (c & 15);
        for (int k0 = l8*4; k0 < HH; k0 += 32)
            *(float4*)&ws[c*WSP_D + k0] = *(const float4*)&g_Wcomb[(size_t)n*HH + k0];
    }
    float bias[4];
    #pragma unroll
    for (int q = 0; q < 4; q++) bias[q] = g_bcomb[q*HH + j];
    float cst[2] = {0.f, 0.f};

    // stage chunk 0 of t=0
    {
        const float* src = g_hA + (size_t)(row0+lr)*HH + t8*8;
        float* dst = hs + 0*HS_BUF + lr*HS_STRIDE + t8*8;
        cpa16(dst, src); cpa16(dst+4, src+4);
        cpa_commit(); cpa_wait0();
    }
    __syncthreads();

    for (int t = 0; t < TT; t++){
        const float* hr = (t & 1) ? g_hB : g_hA;
        float*       hw = (t & 1) ? g_hA : g_hB;

        unsigned long long acc[4][2];
        #pragma unroll
        for (int q = 0; q < 4; q++){ acc[q][0] = 0ull; acc[q][1] = 0ull; }

        int pb = 0;
        for (int cn = 0; cn < NCH_D; cn++){
            if (cn + 1 < NCH_D){
                const float* src = hr + (size_t)(row0+lr)*HH + (cn+1)*64 + t8*8;
                float* dst = hs + (pb^1)*HS_BUF + lr*HS_STRIDE + t8*8;
                cpa16(dst, src); cpa16(dst+4, src+4);
            }
            cpa_commit();
            {
                const float* hb = hs + pb*HS_BUF + (ty*2)*HS_STRIDE;
                const float* wb = ws + tx*WSP_D + cn*64;
                mma_k<16, WSP_D>(acc, hb, wb);
            }
            cpa_wait0();
            __syncthreads();
            pb ^= 1;
        }

        #pragma unroll
        for (int i = 0; i < 2; i++){
            int r = row0 + ty*2 + i;
            float2 v0 = ull2f(acc[0][i]);
            float2 v1 = ull2f(acc[1][i]);
            float2 v2 = ull2f(acc[2][i]);
            float2 v3 = ull2f(acc[3][i]);
            float gi = v0.x + v0.y + bias[0];
            float gf = v1.x + v1.y + bias[1];
            float gg = v2.x + v2.y + bias[2];
            float go = v3.x + v3.y + bias[3];
            if (t == 0){
                gi -= g_corr[(size_t)r*GG + 0*HH + j];
                gf -= g_corr[(size_t)r*GG + 1*HH + j];
                gg -= g_corr[(size_t)r*GG + 2*HH + j];
                go -= g_corr[(size_t)r*GG + 3*HH + j];
            }
            float cn_ = sigf(gf)*cst[i] + sigf(gi)*tanh_f(gg);
            cst[i] = cn_;
            float hv = sigf(go)*tanh_f(cn_);
            hw[(size_t)r*HH + j] = hv;
            g_Hbuf[((size_t)t*BB + r)*HH + j] = hv;
        }
        grid_sync((unsigned)t);

        // stage chunk 0 of next step (needs fresh h, so after grid barrier)
        if (t + 1 < TT){
            const float* hn = (t & 1) ? g_hA : g_hB;
            const float* src = hn + (size_t)(row0+lr)*HH + t8*8;
            float* dst = hs + 0*HS_BUF + lr*HS_STRIDE + t8*8;
            cpa16(dst, src); cpa16(dst+4, src+4);
            cpa_commit(); cpa_wait0();
            __syncthreads();
        }
    }
}

// ---------------- recon head ----------------
__device__ __forceinline__ void stage_h32(float hsb[32][68], const float* __restrict__ src, int stride){
    int kk = threadIdx.x & 31, rb = threadIdx.x >> 5;
    #pragma unroll
    for (int i = 0; i < 8; i++)
        hsb[kk][rb + i*8] = src[(size_t)(rb + i*8)*stride + kk];
}

__global__ void __launch_bounds__(256) k_recon(const float* __restrict__ fcW,
                                               const float* __restrict__ fcb,
                                               float* __restrict__ out){
    __shared__ __align__(16) float hsb[32][68];
    __shared__ unsigned long long wsd[32][DD];
    int t = blockIdx.x;
    int b0 = blockIdx.y * 64;
    int tid = threadIdx.x;
    int txd = tid & 15, tyb = tid >> 4;

    unsigned long long acc[5][2];
    #pragma unroll
    for (int s = 0; s < 5; s++){ acc[s][0] = 0ull; acc[s][1] = 0ull; }

    for (int c = 0; c < 16; c++){
        __syncthreads();
        stage_h32(hsb, g_Hbuf + ((size_t)t*BB + b0)*HH + c*32, HH);
        {
            int kk = tid & 31, db = tid >> 5;
            #pragma unroll
            for (int i = 0; i < 10; i++){
                int d = db + i*8;
                wsd[kk][d] = dupf(fcW[(size_t)d*HH + c*32 + kk]);
            }
        }
        __syncthreads();
        #pragma unroll
        for (int kk = 0; kk < 32; kk++){
            ulonglong2 hp = *(const ulonglong2*)&hsb[kk][tyb*4];
            #pragma unroll
            for (int s = 0; s < 5; s++){
                unsigned long long w = wsd[kk][txd + 16*s];
                ffma2(acc[s][0], hp.x, w);
                ffma2(acc[s][1], hp.y, w);
            }
        }
    }
    #pragma unroll
    for (int s = 0; s < 5; s++){
        int d = txd + 16*s;
        float bv = fcb[d];
        #pragma unroll
        for (int p = 0; p < 2; p++){
            float2 v = ull2f(acc[s][p]);
            int b = b0 + tyb*4 + p*2;
            out[((size_t)b*TT + t)*DD + d]     = v.x + bv;
            out[((size_t)(b+1)*TT + t)*DD + d] = v.y + bv;
        }
    }
}

// ---------------- launcher ----------------
extern "C" void kernel_launch(void* const* d_in, const int* in_sizes, int n_in,
                              void* d_out, int out_size){
    (void)in_sizes; (void)n_in; (void)out_size;
    const float* traj = (const float*)d_in[0];
    const float* eWih = (const float*)d_in[2];
    const float* eWhh = (const float*)d_in[3];
    const float* ebi  = (const float*)d_in[4];
    const float* ebh  = (const float*)d_in[5];
    const float* emb  = (const float*)d_in[6];
    const float* dWih = (const float*)d_in[7];
    const float* dWhh = (const float*)d_in[8];
    const float* dbi  = (const float*)d_in[9];
    const float* dbh  = (const float*)d_in[10];
    const float* fcW  = (const float*)d_in[11];
    const float* fcb  = (const float*)d_in[12];
    float* out = (float*)d_out;

    const int SMEM_E = (64*WSP_E + 2*HS_BUF)*4;   // 187392 B
    const int SMEM_D = (64*WSP_D + 2*HS_BUF)*4;   // 166912 B
    cudaFuncSetAttribute(k_encoder, cudaFuncAttributeMaxDynamicSharedMemorySize, SMEM_E);
    cudaFuncSetAttribute(k_decoder, cudaFuncAttributeMaxDynamicSharedMemorySize, SMEM_D);

    k_bias<<<8, 256>>>(ebi, ebh, dbi, dbh, dWih, fcb);
    k_wcomb<<<512, 256>>>(dWih, dWhh, fcW);
    k_init<<<512, 256>>>();
    k_encoder<<<NBLK, NTH, SMEM_E>>>(traj, eWih, eWhh);
    k_vq<<<BB, 256>>>(emb);
    k_vqfinish<<<1, 256>>>(out);
    k_x1<<<BB, 256>>>(fcW, fcb);
    k_corr<<<GG, 256>>>(dWih);
    k_decinit<<<512, 256>>>();
    k_decoder<<<NBLK, NTH, SMEM_D>>>();
    k_recon<<<dim3(TT, 4), 256>>>(fcW, fcb, out);
}

// round 5
// speedup vs baseline: 2.3871x; 2.3871x over previous
#include <cuda_runtime.h>
#include <cuda_fp16.h>
#include <cstdint>

#define BB 256
#define TT 256
#define DD 80
#define HH 512
#define GG 2048
#define NBLK 128
#define CS 136                 // h chunk smem stride (halves)
#define CHB (128*CS*2)         // one chunk buffer, bytes

// ---------------- device scratch ----------------
__device__ __align__(16) __half g_h16[2][2][(size_t)BB*HH]; // [parity][hi/lo]
__device__ __align__(16) __half g_txh[(size_t)BB*TT*DD];
__device__ __align__(16) __half g_txl[(size_t)BB*TT*DD];
__device__ float g_Wcomb[(size_t)GG*HH];
__device__ float g_bias_enc[GG];
__device__ float g_bcomb[GG];
__device__ float g_quant[BB*HH];
__device__ float g_hA[BB*HH];
__device__ float g_tmpT[DD*BB];
__device__ float g_corr[(size_t)BB*GG];
__device__ float g_lossp[BB];
__device__ int   g_idx[BB];
__device__ float g_Hbuf[(size_t)TT*BB*HH];
__device__ unsigned g_bar;

// ---------------- helpers ----------------
__device__ __forceinline__ unsigned long long dupf(float v){
    unsigned long long r; asm("mov.b64 %0, {%1,%1};" : "=l"(r) : "f"(v)); return r;
}
__device__ __forceinline__ float2 ull2f(unsigned long long v){
    float2 r; asm("mov.b64 {%0,%1}, %2;" : "=f"(r.x), "=f"(r.y) : "l"(v)); return r;
}
__device__ __forceinline__ void ffma2(unsigned long long& d, unsigned long long a, unsigned long long b){
    asm("fma.rn.f32x2 %0, %1, %2, %0;" : "+l"(d) : "l"(a), "l"(b));
}
__device__ __forceinline__ float sigf(float x){ return 1.f/(1.f + __expf(-x)); }
__device__ __forceinline__ float tanh_f(float x){ return 2.f/(1.f + __expf(-2.f*x)) - 1.f; }

__device__ __forceinline__ void cpa16s(uint32_t dst, const void* src){
    asm volatile("cp.async.cg.shared.global [%0], [%1], 16;" :: "r"(dst), "l"(src));
}
__device__ __forceinline__ void cpa_commit(){ asm volatile("cp.async.commit_group;" ::: "memory"); }
__device__ __forceinline__ void cpa_wait0(){ asm volatile("cp.async.wait_group 0;" ::: "memory"); }

__device__ __forceinline__ void ldsm4(uint32_t* r, uint32_t addr){
    asm volatile("ldmatrix.sync.aligned.m8n8.x4.shared.b16 {%0,%1,%2,%3}, [%4];"
        : "=r"(r[0]), "=r"(r[1]), "=r"(r[2]), "=r"(r[3]) : "r"(addr));
}
__device__ __forceinline__ void hmma(float* c, const uint32_t* a, const uint32_t* b){
    asm volatile("mma.sync.aligned.m16n8k16.row.col.f32.f16.f16.f32 "
        "{%0,%1,%2,%3}, {%4,%5,%6,%7}, {%8,%9}, {%0,%1,%2,%3};"
        : "+f"(c[0]), "+f"(c[1]), "+f"(c[2]), "+f"(c[3])
        : "r"(a[0]), "r"(a[1]), "r"(a[2]), "r"(a[3]), "r"(b[0]), "r"(b[1]));
}

__device__ __forceinline__ void grid_sync(unsigned epoch){
    __syncthreads();
    if (threadIdx.x == 0){
        __threadfence();
        atomicAdd(&g_bar, 1u);
        unsigned target = (epoch + 1u) * NBLK;
        unsigned v;
        do {
            asm volatile("ld.acquire.gpu.u32 %0, [%1];" : "=r"(v) : "l"(&g_bar) : "memory");
        } while (v < target);
    }
    __syncthreads();
}

template<int NK>
__device__ __forceinline__ void mma_loop(float acc[4][4], uint32_t aH, uint32_t aL,
                                         uint32_t bH0, uint32_t bH1, uint32_t bL0, uint32_t bL1){
    #pragma unroll
    for (int kk = 0; kk < NK; kk++){
        uint32_t ah[4], al[4], bh0[4], bh1[4], bl0[4], bl1[4];
        ldsm4(ah,  aH  + kk*32);
        ldsm4(al,  aL  + kk*32);
        ldsm4(bh0, bH0 + kk*32);
        ldsm4(bh1, bH1 + kk*32);
        ldsm4(bl0, bL0 + kk*32);
        ldsm4(bl1, bL1 + kk*32);
        hmma(acc[0], ah, bh0);   hmma(acc[1], ah, bh0+2);
        hmma(acc[2], ah, bh1);   hmma(acc[3], ah, bh1+2);
        hmma(acc[0], ah, bl0);   hmma(acc[1], ah, bl0+2);
        hmma(acc[2], ah, bl1);   hmma(acc[3], ah, bl1+2);
        hmma(acc[0], al, bh0);   hmma(acc[1], al, bh0+2);
        hmma(acc[2], al, bh1);   hmma(acc[3], al, bh1+2);
    }
}

// ---------------- prep kernels ----------------
__global__ void k_bias(const float* __restrict__ ebi, const float* __restrict__ ebh,
                       const float* __restrict__ dbi, const float* __restrict__ dbh,
                       const float* __restrict__ dWih, const float* __restrict__ fcb){
    int n = blockIdx.x*blockDim.x + threadIdx.x;
    if (n < GG){
        g_bias_enc[n] = ebi[n] + ebh[n];
        float b = dbi[n] + dbh[n];
        const float* w = dWih + (size_t)n*DD;
        #pragma unroll 4
        for (int d = 0; d < DD; d++) b += fcb[d]*w[d];
        g_bcomb[n] = b;
    }
}

__global__ void k_wcomb(const float* __restrict__ dWih, const float* __restrict__ dWhh,
                        const float* __restrict__ fcW){
    __shared__ float sf[DD][64];
    __shared__ float sw[32][DD];
    int nt = blockIdx.x >> 3, kt = blockIdx.x & 7;
    int n0 = nt*32, k0 = kt*64;
    int tid = threadIdx.x;
    for (int idx = tid; idx < DD*64; idx += 256){
        int d = idx >> 6, kk = idx & 63;
        sf[d][kk] = fcW[(size_t)d*HH + k0 + kk];
    }
    for (int idx = tid; idx < 32*DD; idx += 256){
        int nn = idx / DD, d = idx % DD;
        sw[nn][d] = dWih[(size_t)(n0+nn)*DD + d];
    }
    __syncthreads();
    int nn = tid >> 3, kb = (tid & 7)*8;
    float a[8];
    #pragma unroll
    for (int i = 0; i < 8; i++) a[i] = dWhh[(size_t)(n0+nn)*HH + k0 + kb + i];
    for (int d = 0; d < DD; d++){
        float w = sw[nn][d];
        #pragma unroll
        for (int i = 0; i < 8; i++) a[i] += w * sf[d][kb+i];
    }
    #pragma unroll
    for (int i = 0; i < 8; i++) g_Wcomb[(size_t)(n0+nn)*HH + k0 + kb + i] = a[i];
}

__global__ void k_tx(const float* __restrict__ traj){
    size_t N = (size_t)BB*TT*DD;
    for (size_t i = (size_t)blockIdx.x*blockDim.x + threadIdx.x; i < N; i += (size_t)gridDim.x*blockDim.x){
        float v = traj[i];
        __half h = __float2half_rn(v);
        g_txh[i] = h;
        g_txl[i] = __float2half_rn(v - __half2float(h));
    }
}

__global__ void k_x1(const float* __restrict__ fcW, const float* __restrict__ fcb){
    int b = blockIdx.x, tid = threadIdx.x;
    __shared__ float qs[HH];
    qs[tid]       = g_quant[(size_t)b*HH + tid];
    qs[tid + 256] = g_quant[(size_t)b*HH + tid + 256];
    __syncthreads();
    if (tid < DD){
        const float* w = fcW + (size_t)tid*HH;
        float s = fcb[tid];
        for (int k = 0; k < HH; k++) s += w[k]*qs[k];
        g_tmpT[tid*BB + b] = s;
    }
}

__global__ void k_corr(const float* __restrict__ dWih){
    int n = blockIdx.x, b = threadIdx.x;
    __shared__ float wd[DD];
    if (b < DD) wd[b] = dWih[(size_t)n*DD + b];
    __syncthreads();
    float s = 0.f;
    #pragma unroll 4
    for (int d = 0; d < DD; d++) s += wd[d] * g_tmpT[d*BB + b];
    g_corr[(size_t)b*GG + n] = s;
}

__global__ void k_init(){ if (threadIdx.x == 0 && blockIdx.x == 0) g_bar = 0u; }

__global__ void k_decprep(){
    int i = blockIdx.x*blockDim.x + threadIdx.x;
    if (i < BB*HH){
        float q = g_quant[i];
        __half h = __float2half_rn(q);
        g_h16[0][0][i] = h;
        g_h16[0][1][i] = __float2half_rn(q - __half2float(h));
    }
    if (i == 0) g_bar = 0u;
}

// ---------------- persistent recurrent kernel (HMMA fp16-split) ----------------
template<bool ENC>
__global__ void __launch_bounds__(256, 1) k_rnn(const float* __restrict__ eWih,
                                                const float* __restrict__ eWhh){
    extern __shared__ __half smh[];
    const int SW = ENC ? 600 : 520;      // W smem stride (halves)
    const int KW = ENC ? 592 : 512;
    const int NC = ENC ? 5 : 4;          // chunks (128 k each; enc last = 80 x)
    const uint32_t WHALF = (uint32_t)(32*SW*2);     // bytes per W copy
    const uint32_t HS_OFF = 2u*WHALF;               // hs region start

    const int tid = threadIdx.x;
    const int wid = tid >> 5, lane = tid & 31;
    const int rg = blockIdx.x >> 6, cg = blockIdx.x & 63;
    const int row0 = rg*128, j0 = cg*8;
    const uint32_t smb = (uint32_t)__cvta_generic_to_shared(smh);

    // ---- W fill (hi/lo split), resident all steps ----
    for (int idx = tid; idx < 32*KW; idx += 256){
        int br = idx / KW, k = idx - br*KW;
        int n = (br >> 3)*HH + j0 + (br & 7);
        float v;
        if (ENC) v = (k < HH) ? eWhh[(size_t)n*HH + k] : eWih[(size_t)n*DD + k - HH];
        else     v = g_Wcomb[(size_t)n*HH + k];
        __half h = __float2half_rn(v);
        smh[br*SW + k] = h;
        smh[32*SW + br*SW + k] = __float2half_rn(v - __half2float(h));
    }

    // ---- per-thread constants ----
    const int jj = (lane & 3)*2;
    const int rbase = row0 + wid*16 + (lane >> 2);
    float bias[4][2], corr[2][4][2];
    #pragma unroll
    for (int q = 0; q < 4; q++)
        #pragma unroll
        for (int e = 0; e < 2; e++){
            bias[q][e] = ENC ? g_bias_enc[q*HH + j0 + jj + e] : g_bcomb[q*HH + j0 + jj + e];
            if (!ENC){
                corr[0][q][e] = g_corr[(size_t)rbase*GG + q*HH + j0 + jj + e];
                corr[1][q][e] = g_corr[(size_t)(rbase+8)*GG + q*HH + j0 + jj + e];
            }
        }
    float cst[2][2] = {{0.f,0.f},{0.f,0.f}};

    // ldmatrix per-lane address offsets (bytes)
    const uint32_t laneA = (uint32_t)((wid*16 + (lane & 15))*CS + (lane >> 4)*8)*2;
    const uint32_t laneB = (uint32_t)(((lane & 7) + ((lane >> 4) & 1)*8)*SW + ((lane >> 3) & 1)*8)*2;

    for (int t = 0; t < TT; t++){
        const int img = t & 1;
        const int c0s = (ENC && t == 0) ? NC-1 : 0;
        int buf = 0;

        // ---- stage chunk c0s ----
        {
            int c = c0s;
            uint32_t dstH = smb + HS_OFF + (uint32_t)buf*2u*CHB;
            if (ENC && c == NC-1){
                #pragma unroll
                for (int i = 0; i < 5; i++){
                    int u = tid + i*256;
                    int row = u/10, seg = u - row*10;
                    uint32_t d = dstH + (uint32_t)(row*CS + seg*8)*2;
                    size_t so = ((size_t)(row0+row)*TT + t)*DD + seg*8;
                    cpa16s(d, g_txh + so);
                    cpa16s(d + CHB, g_txl + so);
                }
            } else {
                const __half* sH = g_h16[img][0];
                const __half* sL = g_h16[img][1];
                #pragma unroll
                for (int i = 0; i < 8; i++){
                    int u = tid + i*256;
                    int row = u >> 4, seg = u & 15;
                    uint32_t d = dstH + (uint32_t)(row*CS + seg*8)*2;
                    size_t so = (size_t)(row0+row)*HH + c*128 + seg*8;
                    cpa16s(d, sH + so);
                    cpa16s(d + CHB, sL + so);
                }
            }
            cpa_commit();
        }

        float acc[4][4];
        #pragma unroll
        for (int q = 0; q < 4; q++)
            #pragma unroll
            for (int i = 0; i < 4; i++) acc[q][i] = 0.f;

        for (int c = c0s; c < NC; c++){
            cpa_wait0();
            __syncthreads();
            if (c + 1 < NC){
                int nc = c + 1;
                uint32_t dstH = smb + HS_OFF + (uint32_t)(buf^1)*2u*CHB;
                if (ENC && nc == NC-1){
                    #pragma unroll
                    for (int i = 0; i < 5; i++){
                        int u = tid + i*256;
                        int row = u/10, seg = u - row*10;
                        uint32_t d = dstH + (uint32_t)(row*CS + seg*8)*2;
                        size_t so = ((size_t)(row0+row)*TT + t)*DD + seg*8;
                        cpa16s(d, g_txh + so);
                        cpa16s(d + CHB, g_txl + so);
                    }
                } else {
                    const __half* sH = g_h16[img][0];
                    const __half* sL = g_h16[img][1];
                    #pragma unroll
                    for (int i = 0; i < 8; i++){
                        int u = tid + i*256;
                        int row = u >> 4, seg = u & 15;
                        uint32_t d = dstH + (uint32_t)(row*CS + seg*8)*2;
                        size_t so = (size_t)(row0+row)*HH + nc*128 + seg*8;
                        cpa16s(d, sH + so);
                        cpa16s(d + CHB, sL + so);
                    }
                }
                cpa_commit();
            }
            // ---- MMA on chunk c ----
            {
                uint32_t aH = smb + HS_OFF + (uint32_t)buf*2u*CHB + laneA;
                uint32_t aL = aH + CHB;
                uint32_t b0H = smb + laneB + (uint32_t)(c*128)*2;
                uint32_t b1H = b0H + (uint32_t)(16*SW)*2;
                uint32_t b0L = b0H + WHALF;
                uint32_t b1L = b1H + WHALF;
                if (ENC && c == NC-1) mma_loop<5>(acc, aH, aL, b0H, b1H, b0L, b1L);
                else                  mma_loop<8>(acc, aH, aL, b0H, b1H, b0L, b1L);
            }
            buf ^= 1;
        }

        // ---- epilogue ----
        {
            const int nimg = (t+1) & 1;
            #pragma unroll
            for (int p = 0; p < 2; p++){
                float hv[2];
                #pragma unroll
                for (int e = 0; e < 2; e++){
                    float gi = acc[0][p*2+e] + bias[0][e];
                    float gf = acc[1][p*2+e] + bias[1][e];
                    float gg = acc[2][p*2+e] + bias[2][e];
                    float go = acc[3][p*2+e] + bias[3][e];
                    if (!ENC && t == 0){
                        gi -= corr[p][0][e]; gf -= corr[p][1][e];
                        gg -= corr[p][2][e]; go -= corr[p][3][e];
                    }
                    float cn = sigf(gf)*cst[p][e] + sigf(gi)*tanh_f(gg);
                    cst[p][e] = cn;
                    hv[e] = sigf(go)*tanh_f(cn);
                }
                int r = rbase + p*8;
                __half h0 = __float2half_rn(hv[0]);
                __half h1 = __float2half_rn(hv[1]);
                uint32_t uh = (uint32_t)__half_as_ushort(h0) | ((uint32_t)__half_as_ushort(h1) << 16);
                __half l0 = __float2half_rn(hv[0] - __half2float(h0));
                __half l1 = __float2half_rn(hv[1] - __half2float(h1));
                uint32_t ul = (uint32_t)__half_as_ushort(l0) | ((uint32_t)__half_as_ushort(l1) << 16);
                size_t hidx = (size_t)r*HH + j0 + jj;
                *(uint32_t*)&g_h16[nimg][0][hidx] = uh;
                *(uint32_t*)&g_h16[nimg][1][hidx] = ul;
                if (ENC){
                    if (t == TT-1){
                        g_hA[hidx]     = hv[0];
                        g_hA[hidx + 1] = hv[1];
                    }
                } else {
                    float2 f2; f2.x = hv[0]; f2.y = hv[1];
                    *(float2*)&g_Hbuf[((size_t)t*BB + r)*HH + j0 + jj] = f2;
                }
            }
        }
        grid_sync((unsigned)t);
    }
}

// ---------------- VQ ----------------
__global__ void k_vq(const float* __restrict__ emb){
    int b = blockIdx.x, tid = threadIdx.x;
    __shared__ float zs[HH];
    __shared__ float rs[256];
    __shared__ int   rk[256];
    zs[tid]       = g_hA[(size_t)b*HH + tid];
    zs[tid + 256] = g_hA[(size_t)b*HH + tid + 256];
    __syncthreads();
    float bestS = 3.4e38f; int bestK = 0;
    #pragma unroll
    for (int kq = 0; kq < 2; kq++){
        int k = tid + kq*256;
        const float* e = emb + (size_t)k*HH;
        float s = 0.f, dt = 0.f;
        for (int jj = 0; jj < HH; jj++){ float ev = e[jj]; s += ev*ev; dt += ev*zs[jj]; }
        float score = s - 2.f*dt;
        if (score < bestS || (score == bestS && k < bestK)){ bestS = score; bestK = k; }
    }
    rs[tid] = bestS; rk[tid] = bestK;
    __syncthreads();
    for (int s = 128; s > 0; s >>= 1){
        if (tid < s){
            if (rs[tid+s] < rs[tid] || (rs[tid+s] == rs[tid] && rk[tid+s] < rk[tid])){
                rs[tid] = rs[tid+s]; rk[tid] = rk[tid+s];
            }
        }
        __syncthreads();
    }
    int idx = rk[0];
    if (tid == 0) g_idx[b] = idx;
    float lp = 0.f;
    #pragma unroll
    for (int kq = 0; kq < 2; kq++){
        int jj = tid + kq*256;
        float q = emb[(size_t)idx*HH + jj];
        g_quant[(size_t)b*HH + jj] = q;
        float dz = q - zs[jj];
        lp += dz*dz;
    }
    __syncthreads();
    rs[tid] = lp;
    __syncthreads();
    for (int s = 128; s > 0; s >>= 1){
        if (tid < s) rs[tid] += rs[tid+s];
        __syncthreads();
    }
    if (tid == 0) g_lossp[b] = rs[0];
}

__global__ void k_vqfinish(float* __restrict__ out){
    const size_t OFF = (size_t)BB*TT*DD;
    int tid = threadIdx.x;
    if (tid == 0){
        float tot = 0.f;
        for (int i = 0; i < BB; i++) tot += g_lossp[i];
        out[OFF] = 1.25f * tot / (float)(BB*HH);
    }
    out[OFF + 1 + tid] = (float)g_idx[tid];
}

// ---------------- recon head ----------------
__device__ __forceinline__ void stage_h32r(float hsb[32][68], const float* __restrict__ src, int stride){
    int kk = threadIdx.x & 31, rb = threadIdx.x >> 5;
    #pragma unroll
    for (int i = 0; i < 8; i++)
        hsb[kk][rb + i*8] = src[(size_t)(rb + i*8)*stride + kk];
}

__global__ void __launch_bounds__(256) k_recon(const float* __restrict__ fcW,
                                               const float* __restrict__ fcb,
                                               float* __restrict__ out){
    __shared__ __align__(16) float hsb[32][68];
    __shared__ unsigned long long wsd[32][DD];
    int t = blockIdx.x;
    int b0 = blockIdx.y * 64;
    int tid = threadIdx.x;
    int txd = tid & 15, tyb = tid >> 4;

    unsigned long long acc[5][2];
    #pragma unroll
    for (int s = 0; s < 5; s++){ acc[s][0] = 0ull; acc[s][1] = 0ull; }

    for (int c = 0; c < 16; c++){
        __syncthreads();
        stage_h32r(hsb, g_Hbuf + ((size_t)t*BB + b0)*HH + c*32, HH);
        {
            int kk = tid & 31, db = tid >> 5;
            #pragma unroll
            for (int i = 0; i < 10; i++){
                int d = db + i*8;
                wsd[kk][d] = dupf(fcW[(size_t)d*HH + c*32 + kk]);
            }
        }
        __syncthreads();
        #pragma unroll
        for (int kk = 0; kk < 32; kk++){
            ulonglong2 hp = *(const ulonglong2*)&hsb[kk][tyb*4];
            #pragma unroll
            for (int s = 0; s < 5; s++){
                unsigned long long w = wsd[kk][txd + 16*s];
                ffma2(acc[s][0], hp.x, w);
                ffma2(acc[s][1], hp.y, w);
            }
        }
    }
    #pragma unroll
    for (int s = 0; s < 5; s++){
        int d = txd + 16*s;
        float bv = fcb[d];
        #pragma unroll
        for (int p = 0; p < 2; p++){
            float2 v = ull2f(acc[s][p]);
            int b = b0 + tyb*4 + p*2;
            out[((size_t)b*TT + t)*DD + d]     = v.x + bv;
            out[((size_t)(b+1)*TT + t)*DD + d] = v.y + bv;
        }
    }
}

// ---------------- launcher ----------------
extern "C" void kernel_launch(void* const* d_in, const int* in_sizes, int n_in,
                              void* d_out, int out_size){
    (void)in_sizes; (void)n_in; (void)out_size;
    const float* traj = (const float*)d_in[0];
    const float* eWih = (const float*)d_in[2];
    const float* eWhh = (const float*)d_in[3];
    const float* ebi  = (const float*)d_in[4];
    const float* ebh  = (const float*)d_in[5];
    const float* emb  = (const float*)d_in[6];
    const float* dWih = (const float*)d_in[7];
    const float* dWhh = (const float*)d_in[8];
    const float* dbi  = (const float*)d_in[9];
    const float* dbh  = (const float*)d_in[10];
    const float* fcW  = (const float*)d_in[11];
    const float* fcb  = (const float*)d_in[12];
    float* out = (float*)d_out;

    const int SME = (2*32*600)*2 + 4*CHB;   // 76800 + 139264 = 216064 B
    const int SMD = (2*32*520)*2 + 4*CHB;   // 66560 + 139264 = 205824 B
    cudaFuncSetAttribute(k_rnn<true>,  cudaFuncAttributeMaxDynamicSharedMemorySize, SME);
    cudaFuncSetAttribute(k_rnn<false>, cudaFuncAttributeMaxDynamicSharedMemorySize, SMD);

    k_bias<<<8, 256>>>(ebi, ebh, dbi, dbh, dWih, fcb);
    k_wcomb<<<512, 256>>>(dWih, dWhh, fcW);
    k_tx<<<1024, 256>>>(traj);
    k_init<<<1, 32>>>();
    k_rnn<true><<<NBLK, 256, SME>>>(eWih, eWhh);
    k_vq<<<BB, 256>>>(emb);
    k_vqfinish<<<1, 256>>>(out);
    k_x1<<<BB, 256>>>(fcW, fcb);
    k_corr<<<GG, 256>>>(dWih);
    k_decprep<<<512, 256>>>();
    k_rnn<false><<<NBLK, 256, SMD>>>(eWih, eWhh);
    k_recon<<<dim3(TT, 4), 256>>>(fcW, fcb, out);
}

// round 6
// speedup vs baseline: 3.4036x; 1.4258x over previous
#include <cuda_runtime.h>
#include <cuda_fp16.h>
#include <cstdint>

#define BB 256
#define TT 256
#define DD 80
#define HH 512
#define GG 2048
#define NBLK 128
#define CS 136                 // h chunk smem stride (halves)

// ---------------- device scratch ----------------
__device__ __align__(16) __half g_h16[2][(size_t)BB*HH]; // [parity]
__device__ __align__(16) __half g_txh[(size_t)BB*TT*DD];
__device__ float g_Wcomb[(size_t)GG*HH];
__device__ float g_bias_enc[GG];
__device__ float g_bcomb[GG];
__device__ float g_quant[BB*HH];
__device__ float g_hA[BB*HH];
__device__ float g_tmpT[DD*BB];
__device__ float g_corr[(size_t)BB*GG];
__device__ float g_lossp[BB];
__device__ int   g_idx[BB];
__device__ float g_Hbuf[(size_t)TT*BB*HH];
__device__ unsigned g_bar;

// ---------------- helpers ----------------
__device__ __forceinline__ unsigned long long dupf(float v){
    unsigned long long r; asm("mov.b64 %0, {%1,%1};" : "=l"(r) : "f"(v)); return r;
}
__device__ __forceinline__ float2 ull2f(unsigned long long v){
    float2 r; asm("mov.b64 {%0,%1}, %2;" : "=f"(r.x), "=f"(r.y) : "l"(v)); return r;
}
__device__ __forceinline__ void ffma2(unsigned long long& d, unsigned long long a, unsigned long long b){
    asm("fma.rn.f32x2 %0, %1, %2, %0;" : "+l"(d) : "l"(a), "l"(b));
}
__device__ __forceinline__ float sigf(float x){ return 1.f/(1.f + __expf(-x)); }
__device__ __forceinline__ float tanh_f(float x){ return 2.f/(1.f + __expf(-2.f*x)) - 1.f; }

__device__ __forceinline__ void cpa16s(uint32_t dst, const void* src){
    asm volatile("cp.async.cg.shared.global [%0], [%1], 16;" :: "r"(dst), "l"(src));
}
__device__ __forceinline__ void cpa_commit(){ asm volatile("cp.async.commit_group;" ::: "memory"); }
__device__ __forceinline__ void cpa_wait0(){ asm volatile("cp.async.wait_group 0;" ::: "memory"); }
__device__ __forceinline__ void cpa_wait1(){ asm volatile("cp.async.wait_group 1;" ::: "memory"); }

__device__ __forceinline__ void ldsm4(uint32_t* r, uint32_t addr){
    asm volatile("ldmatrix.sync.aligned.m8n8.x4.shared.b16 {%0,%1,%2,%3}, [%4];"
        : "=r"(r[0]), "=r"(r[1]), "=r"(r[2]), "=r"(r[3]) : "r"(addr));
}
__device__ __forceinline__ void hmma(float* c, const uint32_t* a, const uint32_t* b){
    asm volatile("mma.sync.aligned.m16n8k16.row.col.f32.f16.f16.f32 "
        "{%0,%1,%2,%3}, {%4,%5,%6,%7}, {%8,%9}, {%0,%1,%2,%3};"
        : "+f"(c[0]), "+f"(c[1]), "+f"(c[2]), "+f"(c[3])
        : "r"(a[0]), "r"(a[1]), "r"(a[2]), "r"(a[3]), "r"(b[0]), "r"(b[1]));
}

__device__ __forceinline__ void grid_sync(unsigned epoch){
    __syncthreads();
    if (threadIdx.x == 0){
        __threadfence();
        atomicAdd(&g_bar, 1u);
        unsigned target = (epoch + 1u) * NBLK;
        unsigned v;
        do {
            asm volatile("ld.acquire.gpu.u32 %0, [%1];" : "=r"(v) : "l"(&g_bar) : "memory");
        } while (v < target);
    }
    __syncthreads();
}

// 2-term MMA over one chunk: acc[gate][4]
template<int NK, int SW>
__device__ __forceinline__ void mma_loop(float acc[4][4], uint32_t aA,
                                         uint32_t bH, uint32_t bL){
    #pragma unroll
    for (int kk = 0; kk < NK; kk++){
        uint32_t ah[4], bh0[4], bh1[4], bl0[4], bl1[4];
        ldsm4(ah,  aA + kk*32);
        ldsm4(bh0, bH + kk*32);
        ldsm4(bh1, bH + 16*SW*2 + kk*32);
        ldsm4(bl0, bL + kk*32);
        ldsm4(bl1, bL + 16*SW*2 + kk*32);
        hmma(acc[0], ah, bh0);   hmma(acc[1], ah, bh0+2);
        hmma(acc[2], ah, bh1);   hmma(acc[3], ah, bh1+2);
        hmma(acc[0], ah, bl0);   hmma(acc[1], ah, bl0+2);
        hmma(acc[2], ah, bl1);   hmma(acc[3], ah, bl1+2);
    }
}

// ---------------- prep kernels ----------------
__global__ void k_bias(const float* __restrict__ ebi, const float* __restrict__ ebh,
                       const float* __restrict__ dbi, const float* __restrict__ dbh,
                       const float* __restrict__ dWih, const float* __restrict__ fcb){
    int n = blockIdx.x*blockDim.x + threadIdx.x;
    if (n < GG){
        g_bias_enc[n] = ebi[n] + ebh[n];
        float b = dbi[n] + dbh[n];
        const float* w = dWih + (size_t)n*DD;
        #pragma unroll 4
        for (int d = 0; d < DD; d++) b += fcb[d]*w[d];
        g_bcomb[n] = b;
    }
}

__global__ void k_wcomb(const float* __restrict__ dWih, const float* __restrict__ dWhh,
                        const float* __restrict__ fcW){
    __shared__ float sf[DD][64];
    __shared__ float sw[32][DD];
    int nt = blockIdx.x >> 3, kt = blockIdx.x & 7;
    int n0 = nt*32, k0 = kt*64;
    int tid = threadIdx.x;
    for (int idx = tid; idx < DD*64; idx += 256){
        int d = idx >> 6, kk = idx & 63;
        sf[d][kk] = fcW[(size_t)d*HH + k0 + kk];
    }
    for (int idx = tid; idx < 32*DD; idx += 256){
        int nn = idx / DD, d = idx % DD;
        sw[nn][d] = dWih[(size_t)(n0+nn)*DD + d];
    }
    __syncthreads();
    int nn = tid >> 3, kb = (tid & 7)*8;
    float a[8];
    #pragma unroll
    for (int i = 0; i < 8; i++) a[i] = dWhh[(size_t)(n0+nn)*HH + k0 + kb + i];
    for (int d = 0; d < DD; d++){
        float w = sw[nn][d];
        #pragma unroll
        for (int i = 0; i < 8; i++) a[i] += w * sf[d][kb+i];
    }
    #pragma unroll
    for (int i = 0; i < 8; i++) g_Wcomb[(size_t)(n0+nn)*HH + k0 + kb + i] = a[i];
}

__global__ void k_tx(const float* __restrict__ traj){
    size_t N = (size_t)BB*TT*DD;
    for (size_t i = (size_t)blockIdx.x*blockDim.x + threadIdx.x; i < N; i += (size_t)gridDim.x*blockDim.x)
        g_txh[i] = __float2half_rn(traj[i]);
}

__global__ void k_x1(const float* __restrict__ fcW, const float* __restrict__ fcb){
    int b = blockIdx.x, tid = threadIdx.x;
    __shared__ float qs[HH];
    qs[tid]       = g_quant[(size_t)b*HH + tid];
    qs[tid + 256] = g_quant[(size_t)b*HH + tid + 256];
    __syncthreads();
    if (tid < DD){
        const float* w = fcW + (size_t)tid*HH;
        float s = fcb[tid];
        for (int k = 0; k < HH; k++) s += w[k]*qs[k];
        g_tmpT[tid*BB + b] = s;
    }
}

__global__ void k_corr(const float* __restrict__ dWih){
    int n = blockIdx.x, b = threadIdx.x;
    __shared__ float wd[DD];
    if (b < DD) wd[b] = dWih[(size_t)n*DD + b];
    __syncthreads();
    float s = 0.f;
    #pragma unroll 4
    for (int d = 0; d < DD; d++) s += wd[d] * g_tmpT[d*BB + b];
    g_corr[(size_t)b*GG + n] = s;
}

__global__ void k_init(){ if (threadIdx.x == 0 && blockIdx.x == 0) g_bar = 0u; }

__global__ void k_decprep(){
    int i = blockIdx.x*blockDim.x + threadIdx.x;
    if (i < BB*HH) g_h16[0][i] = __float2half_rn(g_quant[i]);
    if (i == 0) g_bar = 0u;
}

// ---------------- persistent recurrent kernel ----------------
// Block: 64 batch rows x 64 gate-cols (16 j x 4 gates). 8 warps = 4 M x 2 N.
// Chunks (enc): c0 = x (K 512..591), c1..c4 = h. Chunks (dec): c0..c3 = h.
template<bool ENC>
__global__ void __launch_bounds__(256, 1) k_rnn(const float* __restrict__ eWih,
                                                const float* __restrict__ eWhh){
    extern __shared__ __half smh[];
    constexpr int SW = ENC ? 600 : 520;
    constexpr int KW = ENC ? 592 : 512;
    constexpr int NC = ENC ? 5 : 4;
    const uint32_t WREG = (uint32_t)(64*SW*2);   // bytes per W copy
    const uint32_t HS_OFF = 2u*WREG;
    const uint32_t BUFB = (uint32_t)(64*CS*2);

    const int tid = threadIdx.x;
    const int wid = tid >> 5, lane = tid & 31;
    const int wm = wid & 3, wn = wid >> 2;
    const int rg = blockIdx.x >> 5, cg = blockIdx.x & 31;
    const int row0 = rg*64, j0 = cg*16;
    const uint32_t smb = (uint32_t)__cvta_generic_to_shared(smh);

    // ---- W fill (hi/lo split), resident all steps ----
    for (int idx = tid; idx < 64*KW; idx += 256){
        int br = idx / KW, k = idx - br*KW;
        int n = ((br >> 3) & 3)*HH + j0 + (br >> 5)*8 + (br & 7);
        float v;
        if (ENC) v = (k < HH) ? eWhh[(size_t)n*HH + k] : eWih[(size_t)n*DD + k - HH];
        else     v = g_Wcomb[(size_t)n*HH + k];
        __half h = __float2half_rn(v);
        smh[br*SW + k] = h;
        smh[64*SW + br*SW + k] = __float2half_rn(v - __half2float(h));
    }

    const int j0w = j0 + wn*8;
    const int jj = (lane & 3)*2;
    const int rbase = row0 + wm*16 + (lane >> 2);
    float bias[4][2], corr[2][4][2];
    #pragma unroll
    for (int q = 0; q < 4; q++)
        #pragma unroll
        for (int e = 0; e < 2; e++){
            bias[q][e] = ENC ? g_bias_enc[q*HH + j0w + jj + e] : g_bcomb[q*HH + j0w + jj + e];
            if (!ENC){
                corr[0][q][e] = g_corr[(size_t)rbase*GG + q*HH + j0w + jj + e];
                corr[1][q][e] = g_corr[(size_t)(rbase+8)*GG + q*HH + j0w + jj + e];
            }
        }
    float cst[2][2] = {{0.f,0.f},{0.f,0.f}};

    const uint32_t laneA = (uint32_t)((wm*16 + (lane & 15))*CS + (lane >> 4)*8)*2;
    const uint32_t laneB = (uint32_t)(((lane & 7) + ((lane >> 4) & 1)*8 + wn*32)*SW + ((lane >> 3) & 1)*8)*2;

    // stage chunk c of step t into buffer buf
    auto stage = [&](int buf, int c, int t){
        uint32_t dst = smb + HS_OFF + (uint32_t)buf*BUFB;
        if (ENC && c == 0){
            #pragma unroll
            for (int i = 0; i < 3; i++){
                int u = tid + i*256;
                if (u < 640){
                    int row = u/10, seg = u - row*10;
                    cpa16s(dst + (uint32_t)(row*CS + seg*8)*2,
                           g_txh + ((size_t)(row0+row)*TT + t)*DD + seg*8);
                }
            }
        } else {
            const __half* src = g_h16[t & 1];
            int kb = ENC ? (c-1)*128 : c*128;
            #pragma unroll
            for (int i = 0; i < 4; i++){
                int u = tid + i*256;
                int row = u >> 4, seg = u & 15;
                cpa16s(dst + (uint32_t)(row*CS + seg*8)*2,
                       src + (size_t)(row0+row)*HH + kb + seg*8);
            }
        }
        cpa_commit();
    };

    __syncthreads();
    if (ENC) stage(0, 0, 0);   // x(0), nothing depends on h

    for (int t = 0; t < TT; t++){
        if (!ENC) stage(0, 0, t);
        const int nc = (ENC && t == 0) ? 1 : NC;
        if (nc > 1) stage(1, 1, t);

        float acc[4][4];
        #pragma unroll
        for (int q = 0; q < 4; q++)
            #pragma unroll
            for (int i = 0; i < 4; i++) acc[q][i] = 0.f;

        for (int c = 0; c < nc; c++){
            if (c < nc-1) cpa_wait1(); else cpa_wait0();
            __syncthreads();
            if (c + 2 < nc) stage((c+2)%3, c+2, t);
            {
                uint32_t aA = smb + HS_OFF + (uint32_t)(c%3)*BUFB + laneA;
                int koff = (ENC && c == 0) ? 512 : (ENC ? (c-1)*128 : c*128);
                uint32_t bH = smb + laneB + (uint32_t)koff*2;
                uint32_t bL = bH + WREG;
                if (ENC && c == 0) mma_loop<5, SW>(acc, aA, bH, bL);
                else               mma_loop<8, SW>(acc, aA, bH, bL);
            }
        }
        __syncthreads();

        // ---- epilogue ----
        {
            const int nimg = (t+1) & 1;
            #pragma unroll
            for (int p = 0; p < 2; p++){
                float hv[2];
                #pragma unroll
                for (int e = 0; e < 2; e++){
                    float gi = acc[0][p*2+e] + bias[0][e];
                    float gf = acc[1][p*2+e] + bias[1][e];
                    float gg = acc[2][p*2+e] + bias[2][e];
                    float go = acc[3][p*2+e] + bias[3][e];
                    if (!ENC && t == 0){
                        gi -= corr[p][0][e]; gf -= corr[p][1][e];
                        gg -= corr[p][2][e]; go -= corr[p][3][e];
                    }
                    float cn = sigf(gf)*cst[p][e] + sigf(gi)*tanh_f(gg);
                    cst[p][e] = cn;
                    hv[e] = sigf(go)*tanh_f(cn);
                }
                int r = rbase + p*8;
                __half h0 = __float2half_rn(hv[0]);
                __half h1 = __float2half_rn(hv[1]);
                uint32_t uh = (uint32_t)__half_as_ushort(h0) | ((uint32_t)__half_as_ushort(h1) << 16);
                size_t hidx = (size_t)r*HH + j0w + jj;
                *(uint32_t*)&g_h16[nimg][hidx] = uh;
                if (ENC){
                    if (t == TT-1){
                        g_hA[hidx]     = hv[0];
                        g_hA[hidx + 1] = hv[1];
                    }
                } else {
                    float2 f2; f2.x = hv[0]; f2.y = hv[1];
                    *(float2*)&g_Hbuf[((size_t)t*BB + r)*HH + j0w + jj] = f2;
                }
            }
        }
        if (ENC && t + 1 < TT) stage(0, 0, t+1);   // x(t+1) across the barrier
        grid_sync((unsigned)t);
    }
}

// ---------------- VQ ----------------
__global__ void k_vq(const float* __restrict__ emb){
    int b = blockIdx.x, tid = threadIdx.x;
    __shared__ float zs[HH];
    __shared__ float rs[256];
    __shared__ int   rk[256];
    zs[tid]       = g_hA[(size_t)b*HH + tid];
    zs[tid + 256] = g_hA[(size_t)b*HH + tid + 256];
    __syncthreads();
    float bestS = 3.4e38f; int bestK = 0;
    #pragma unroll
    for (int kq = 0; kq < 2; kq++){
        int k = tid + kq*256;
        const float* e = emb + (size_t)k*HH;
        float s = 0.f, dt = 0.f;
        for (int jj = 0; jj < HH; jj++){ float ev = e[jj]; s += ev*ev; dt += ev*zs[jj]; }
        float score = s - 2.f*dt;
        if (score < bestS || (score == bestS && k < bestK)){ bestS = score; bestK = k; }
    }
    rs[tid] = bestS; rk[tid] = bestK;
    __syncthreads();
    for (int s = 128; s > 0; s >>= 1){
        if (tid < s){
            if (rs[tid+s] < rs[tid] || (rs[tid+s] == rs[tid] && rk[tid+s] < rk[tid])){
                rs[tid] = rs[tid+s]; rk[tid] = rk[tid+s];
            }
        }
        __syncthreads();
    }
    int idx = rk[0];
    if (tid == 0) g_idx[b] = idx;
    float lp = 0.f;
    #pragma unroll
    for (int kq = 0; kq < 2; kq++){
        int jj = tid + kq*256;
        float q = emb[(size_t)idx*HH + jj];
        g_quant[(size_t)b*HH + jj] = q;
        float dz = q - zs[jj];
        lp += dz*dz;
    }
    __syncthreads();
    rs[tid] = lp;
    __syncthreads();
    for (int s = 128; s > 0; s >>= 1){
        if (tid < s) rs[tid] += rs[tid+s];
        __syncthreads();
    }
    if (tid == 0) g_lossp[b] = rs[0];
}

__global__ void k_vqfinish(float* __restrict__ out){
    const size_t OFF = (size_t)BB*TT*DD;
    int tid = threadIdx.x;
    if (tid == 0){
        float tot = 0.f;
        for (int i = 0; i < BB; i++) tot += g_lossp[i];
        out[OFF] = 1.25f * tot / (float)(BB*HH);
    }
    out[OFF + 1 + tid] = (float)g_idx[tid];
}

// ---------------- recon head ----------------
__device__ __forceinline__ void stage_h32r(float hsb[32][68], const float* __restrict__ src, int stride){
    int kk = threadIdx.x & 31, rb = threadIdx.x >> 5;
    #pragma unroll
    for (int i = 0; i < 8; i++)
        hsb[kk][rb + i*8] = src[(size_t)(rb + i*8)*stride + kk];
}

__global__ void __launch_bounds__(256) k_recon(const float* __restrict__ fcW,
                                               const float* __restrict__ fcb,
                                               float* __restrict__ out){
    __shared__ __align__(16) float hsb[32][68];
    __shared__ unsigned long long wsd[32][DD];
    int t = blockIdx.x;
    int b0 = blockIdx.y * 64;
    int tid = threadIdx.x;
    int txd = tid & 15, tyb = tid >> 4;

    unsigned long long acc[5][2];
    #pragma unroll
    for (int s = 0; s < 5; s++){ acc[s][0] = 0ull; acc[s][1] = 0ull; }

    for (int c = 0; c < 16; c++){
        __syncthreads();
        stage_h32r(hsb, g_Hbuf + ((size_t)t*BB + b0)*HH + c*32, HH);
        {
            int kk = tid & 31, db = tid >> 5;
            #pragma unroll
            for (int i = 0; i < 10; i++){
                int d = db + i*8;
                wsd[kk][d] = dupf(fcW[(size_t)d*HH + c*32 + kk]);
            }
        }
        __syncthreads();
        #pragma unroll
        for (int kk = 0; kk < 32; kk++){
            ulonglong2 hp = *(const ulonglong2*)&hsb[kk][tyb*4];
            #pragma unroll
            for (int s = 0; s < 5; s++){
                unsigned long long w = wsd[kk][txd + 16*s];
                ffma2(acc[s][0], hp.x, w);
                ffma2(acc[s][1], hp.y, w);
            }
        }
    }
    #pragma unroll
    for (int s = 0; s < 5; s++){
        int d = txd + 16*s;
        float bv = fcb[d];
        #pragma unroll
        for (int p = 0; p < 2; p++){
            float2 v = ull2f(acc[s][p]);
            int b = b0 + tyb*4 + p*2;
            out[((size_t)b*TT + t)*DD + d]     = v.x + bv;
            out[((size_t)(b+1)*TT + t)*DD + d] = v.y + bv;
        }
    }
}

// ---------------- launcher ----------------
extern "C" void kernel_launch(void* const* d_in, const int* in_sizes, int n_in,
                              void* d_out, int out_size){
    (void)in_sizes; (void)n_in; (void)out_size;
    const float* traj = (const float*)d_in[0];
    const float* eWih = (const float*)d_in[2];
    const float* eWhh = (const float*)d_in[3];
    const float* ebi  = (const float*)d_in[4];
    const float* ebh  = (const float*)d_in[5];
    const float* emb  = (const float*)d_in[6];
    const float* dWih = (const float*)d_in[7];
    const float* dWhh = (const float*)d_in[8];
    const float* dbi  = (const float*)d_in[9];
    const float* dbh  = (const float*)d_in[10];
    const float* fcW  = (const float*)d_in[11];
    const float* fcb  = (const float*)d_in[12];
    float* out = (float*)d_out;

    const int SME = (2*64*600 + 3*64*CS)*2;   // 205824 B
    const int SMD = (2*64*520 + 3*64*CS)*2;   // 185344 B
    cudaFuncSetAttribute(k_rnn<true>,  cudaFuncAttributeMaxDynamicSharedMemorySize, SME);
    cudaFuncSetAttribute(k_rnn<false>, cudaFuncAttributeMaxDynamicSharedMemorySize, SMD);

    k_bias<<<8, 256>>>(ebi, ebh, dbi, dbh, dWih, fcb);
    k_wcomb<<<512, 256>>>(dWih, dWhh, fcW);
    k_tx<<<1024, 256>>>(traj);
    k_init<<<1, 32>>>();
    k_rnn<true><<<NBLK, 256, SME>>>(eWih, eWhh);
    k_vq<<<BB, 256>>>(emb);
    k_vqfinish<<<1, 256>>>(out);
    k_x1<<<BB, 256>>>(fcW, fcb);
    k_corr<<<GG, 256>>>(dWih);
    k_decprep<<<512, 256>>>();
    k_rnn<false><<<NBLK, 256, SMD>>>(eWih, eWhh);
    k_recon<<<dim3(TT, 4), 256>>>(fcW, fcb, out);
}